// round 6
// baseline (speedup 1.0000x reference)
#include <cuda_runtime.h>
#include <cuda_bf16.h>
#include <cstdint>

#define Nn 19
#define GH 64
#define GE 64
#define Bb 256
#define Tt 256
#define BT (Bb*Tt)
#define LH 64
#define G4 256  // 4*LH

// Scratch (device globals; no allocation allowed)
__device__ float g_emb[(size_t)BT * GE];    // (B*T, 64)
__device__ float g_xg0[(size_t)BT * G4];    // (B*T, 256) = emb@Wih0^T + bih0+bhh0

__device__ __forceinline__ float sigmoidf_(float x) {
    return __fdividef(1.f, 1.f + __expf(-x));
}
__device__ __forceinline__ float tanhf_fast(float x) {
    x = fmaxf(x, -30.f);                 // avoid exp overflow -> NaN
    float e = __expf(-2.f * x);          // x large positive: e->0 -> 1
    return __fdividef(1.f - e, 1.f + e);
}

// ---------------------------------------------------------------------------
// Kernel 1: graph encoder. One 64-thread CTA processes many (b,t) graphs.
// Thread j owns output feature column j. Weights live in registers for the
// whole kernel; A / An / X1 staged in shared memory (broadcast reads).
// ---------------------------------------------------------------------------
__global__ __launch_bounds__(64, 8)
void encoder_kernel(const float* __restrict__ conn, const int* __restrict__ mask,
                    const float* __restrict__ w1_w, const float* __restrict__ w1_b,
                    const float* __restrict__ w2_w, const float* __restrict__ w2_b)
{
    __shared__ float As[Nn * Nn];
    __shared__ float Ans[Nn * Nn];
    __shared__ float dis[Nn];
    __shared__ __align__(16) float X1s[Nn * GE];

    const int tid = threadIdx.x;

    // per-thread weight rows (row j of w1_w (64x19) and w2_w (64x64))
    float w1r[Nn];
#pragma unroll
    for (int k = 0; k < Nn; k++) w1r[k] = w1_w[tid * Nn + k];
    float w2r[GE];
#pragma unroll
    for (int k = 0; k < GE; k++) w2r[k] = w2_w[tid * GE + k];
    const float b1 = w1_b[tid];
    const float b2 = w2_b[tid];

    for (int bt = blockIdx.x; bt < BT; bt += gridDim.x) {
        __syncthreads();  // protect smem reuse across iterations
        const float* A = conn + (size_t)bt * (Nn * Nn);
        for (int idx = tid; idx < Nn * Nn; idx += 64) As[idx] = A[idx];
        __syncthreads();
        if (tid < Nn) {
            float d = 1.f;  // +I contribution to row sum
#pragma unroll
            for (int k = 0; k < Nn; k++) d += As[tid * Nn + k];
            dis[tid] = rsqrtf(fmaxf(d, 1e-6f));
        }
        __syncthreads();
        for (int idx = tid; idx < Nn * Nn; idx += 64) {
            int i = idx / Nn, k = idx - i * Nn;
            float a = As[idx] + (i == k ? 1.f : 0.f);
            Ans[idx] = a * dis[i] * dis[k];
        }
        __syncthreads();

        // H1 column j:  H1[i][j] = sum_k A[i][k] * w1[j][k] + b1[j]
        float H[Nn];
#pragma unroll
        for (int i = 0; i < Nn; i++) {
            float acc = b1;
#pragma unroll
            for (int k = 0; k < Nn; k++) acc = fmaf(As[i * Nn + k], w1r[k], acc);
            H[i] = acc;
        }
        // X1 = relu(An @ H1)  (column j fully local), store to smem
#pragma unroll
        for (int i = 0; i < Nn; i++) {
            float acc = 0.f;
#pragma unroll
            for (int k = 0; k < Nn; k++) acc = fmaf(Ans[i * Nn + k], H[k], acc);
            X1s[i * GE + tid] = fmaxf(acc, 0.f);
        }
        __syncthreads();

        // H2 column j: H2[i][j] = sum_k X1[i][k] * w2[j][k] + b2[j]
#pragma unroll
        for (int i = 0; i < Nn; i++) {
            float acc = b2;
#pragma unroll
            for (int k = 0; k < GE; k += 4) {
                float4 x = *reinterpret_cast<const float4*>(&X1s[i * GE + k]);
                acc = fmaf(x.x, w2r[k],     acc);
                acc = fmaf(x.y, w2r[k + 1], acc);
                acc = fmaf(x.z, w2r[k + 2], acc);
                acc = fmaf(x.w, w2r[k + 3], acc);
            }
            H[i] = acc;
        }
        // X2 = relu(An @ H2), mean over nodes, apply mask
        float s = 0.f;
#pragma unroll
        for (int i = 0; i < Nn; i++) {
            float acc = 0.f;
#pragma unroll
            for (int k = 0; k < Nn; k++) acc = fmaf(Ans[i * Nn + k], H[k], acc);
            s += fmaxf(acc, 0.f);
        }
        float mf = (float)mask[bt];
        g_emb[(size_t)bt * GE + tid] = s * (1.f / 19.f) * mf;
    }
}

// ---------------------------------------------------------------------------
// Kernel 2: xg0 = emb @ Wih0^T + (bih0+bhh0).  (65536,64)@(64,256).
// Thread g owns gate column g; 64-row emb tile in smem (broadcast reads).
// ---------------------------------------------------------------------------
__global__ __launch_bounds__(256, 3)
void xg_kernel(const float* __restrict__ Wih0, const float* __restrict__ bih0,
               const float* __restrict__ bhh0)
{
    __shared__ __align__(16) float es[64 * GE];
    const int tid = threadIdx.x;
    float w[GE];
#pragma unroll
    for (int k = 0; k < GE; k++) w[k] = Wih0[tid * GE + k];
    const float bias = bih0[tid] + bhh0[tid];

    const float* ep = g_emb + (size_t)blockIdx.x * 64 * GE;
    for (int idx = tid; idx < 64 * GE; idx += 256) es[idx] = ep[idx];
    __syncthreads();

    float* op = g_xg0 + (size_t)blockIdx.x * 64 * G4;
    for (int r = 0; r < 64; r++) {
        float acc = bias;
#pragma unroll
        for (int k = 0; k < GE; k += 4) {
            float4 e = *reinterpret_cast<const float4*>(&es[r * GE + k]);
            acc = fmaf(e.x, w[k],     acc);
            acc = fmaf(e.y, w[k + 1], acc);
            acc = fmaf(e.z, w[k + 2], acc);
            acc = fmaf(e.w, w[k + 3], acc);
        }
        op[r * G4 + tid] = acc;
    }
}

// ---------------------------------------------------------------------------
// Kernel 3: fused 2-layer LSTM + FC head. 128 CTAs, 2 batch rows each.
// 384 threads = 3 groups x 128 threads:
//   m=0: layer0 gates (xg0[t] + Whh0 @ h0)       -- also does layer0 update
//   m=1: layer1 Wih1 @ h0[t-1] partial           -- also does layer1 update
//   m=2: layer1 Whh1 @ h1[t-2] partial + biases
// Software pipeline: layer1 runs one step behind layer0 -> all groups busy.
// Each thread owns gates g and g+128 for both batch rows (weights in regs).
// ---------------------------------------------------------------------------
__global__ __launch_bounds__(384)
void lstm_kernel(const int* __restrict__ mask,
                 const float* __restrict__ Whh0,
                 const float* __restrict__ Wih1, const float* __restrict__ Whh1,
                 const float* __restrict__ bih1, const float* __restrict__ bhh1,
                 const float* __restrict__ fc1_w, const float* __restrict__ fc1_b,
                 const float* __restrict__ fc2_w, const float* __restrict__ fc2_b,
                 float* __restrict__ out)
{
    __shared__ __align__(16) float h0s[2][LH];
    __shared__ __align__(16) float h1s[2][LH];
    __shared__ float c0s[2][LH], c1s[2][LH];
    __shared__ float a0buf[2][G4], p1buf[2][G4], p2buf[2][G4];
    __shared__ float lasth[2][LH];
    __shared__ float r1s[2][32];
    __shared__ int lastidx[2];

    const int tid = threadIdx.x;
    const int m = tid >> 7;       // group 0..2 (warp-aligned: 4 warps each)
    const int g = tid & 127;      // gate base; this thread does g and g+128
    const int b0 = blockIdx.x * 2;

    const float* W = (m == 0) ? Whh0 : (m == 1) ? Wih1 : Whh1;
    float wa[LH], wb[LH];
#pragma unroll
    for (int k = 0; k < LH; k++) wa[k] = W[g * LH + k];
#pragma unroll
    for (int k = 0; k < LH; k++) wb[k] = W[(g + 128) * LH + k];
    float biasA = 0.f, biasB = 0.f;
    if (m == 2) { biasA = bih1[g] + bhh1[g]; biasB = bih1[g + 128] + bhh1[g + 128]; }

    if (tid < 2 * LH) {
        int bb = tid >> 6, j = tid & 63;
        h0s[bb][j] = 0.f; c0s[bb][j] = 0.f;
        h1s[bb][j] = 0.f; c1s[bb][j] = 0.f;
        lasth[bb][j] = 0.f;
    }
    if (tid < 2) {
        const int* mp = mask + (size_t)(b0 + tid) * Tt;
        int sum = 0;
        for (int t = 0; t < Tt; t++) sum += mp[t];
        lastidx[tid] = max(sum, 1) - 1;
    }
    __syncthreads();

    float xga[2], xgb[2];
    if (m == 0) {
#pragma unroll
        for (int bb = 0; bb < 2; bb++) {
            const float* xp = g_xg0 + (size_t)(b0 + bb) * Tt * G4;
            xga[bb] = xp[g]; xgb[bb] = xp[g + 128];
        }
    }

    for (int s = 0; s <= Tt; s++) {
        // ---- compute phase ----
        if (m == 0) {
            if (s < Tt) {
#pragma unroll
                for (int bb = 0; bb < 2; bb++) {
                    float accA = xga[bb], accB = xgb[bb];
#pragma unroll
                    for (int k = 0; k < LH; k += 4) {
                        float4 h = *reinterpret_cast<const float4*>(&h0s[bb][k]);
                        accA = fmaf(wa[k],     h.x, accA); accB = fmaf(wb[k],     h.x, accB);
                        accA = fmaf(wa[k + 1], h.y, accA); accB = fmaf(wb[k + 1], h.y, accB);
                        accA = fmaf(wa[k + 2], h.z, accA); accB = fmaf(wb[k + 2], h.z, accB);
                        accA = fmaf(wa[k + 3], h.w, accA); accB = fmaf(wb[k + 3], h.w, accB);
                    }
                    a0buf[bb][g] = accA; a0buf[bb][g + 128] = accB;
                }
                if (s + 1 < Tt) {  // prefetch next step's xg0
#pragma unroll
                    for (int bb = 0; bb < 2; bb++) {
                        const float* xp = g_xg0 + ((size_t)(b0 + bb) * Tt + (s + 1)) * G4;
                        xga[bb] = xp[g]; xgb[bb] = xp[g + 128];
                    }
                }
            }
        } else if (m == 1) {
            if (s >= 1) {
#pragma unroll
                for (int bb = 0; bb < 2; bb++) {
                    float accA = 0.f, accB = 0.f;
#pragma unroll
                    for (int k = 0; k < LH; k += 4) {
                        float4 h = *reinterpret_cast<const float4*>(&h0s[bb][k]);
                        accA = fmaf(wa[k],     h.x, accA); accB = fmaf(wb[k],     h.x, accB);
                        accA = fmaf(wa[k + 1], h.y, accA); accB = fmaf(wb[k + 1], h.y, accB);
                        accA = fmaf(wa[k + 2], h.z, accA); accB = fmaf(wb[k + 2], h.z, accB);
                        accA = fmaf(wa[k + 3], h.w, accA); accB = fmaf(wb[k + 3], h.w, accB);
                    }
                    p1buf[bb][g] = accA; p1buf[bb][g + 128] = accB;
                }
            }
        } else {
            if (s >= 1) {
#pragma unroll
                for (int bb = 0; bb < 2; bb++) {
                    float accA = biasA, accB = biasB;
#pragma unroll
                    for (int k = 0; k < LH; k += 4) {
                        float4 h = *reinterpret_cast<const float4*>(&h1s[bb][k]);
                        accA = fmaf(wa[k],     h.x, accA); accB = fmaf(wb[k],     h.x, accB);
                        accA = fmaf(wa[k + 1], h.y, accA); accB = fmaf(wb[k + 1], h.y, accB);
                        accA = fmaf(wa[k + 2], h.z, accA); accB = fmaf(wb[k + 2], h.z, accB);
                        accA = fmaf(wa[k + 3], h.w, accA); accB = fmaf(wb[k + 3], h.w, accB);
                    }
                    p2buf[bb][g] = accA; p2buf[bb][g + 128] = accB;
                }
            }
        }
        __syncthreads();

        // ---- update phase ----
        if (m == 0 && s < Tt) {  // layer0 state update for step s
            int bb = g >> 6, j = g & 63;
            float gi = a0buf[bb][j];
            float gf = a0buf[bb][j + 64];
            float gg = a0buf[bb][j + 128];
            float go = a0buf[bb][j + 192];
            float c = sigmoidf_(gf) * c0s[bb][j] + sigmoidf_(gi) * tanhf_fast(gg);
            c0s[bb][j] = c;
            h0s[bb][j] = sigmoidf_(go) * tanhf_fast(c);
        }
        if (m == 1 && s >= 1) {  // layer1 state update for step s-1
            int bb = g >> 6, j = g & 63;
            float gi = p1buf[bb][j]       + p2buf[bb][j];
            float gf = p1buf[bb][j + 64]  + p2buf[bb][j + 64];
            float gg = p1buf[bb][j + 128] + p2buf[bb][j + 128];
            float go = p1buf[bb][j + 192] + p2buf[bb][j + 192];
            float c = sigmoidf_(gf) * c1s[bb][j] + sigmoidf_(gi) * tanhf_fast(gg);
            c1s[bb][j] = c;
            float h = sigmoidf_(go) * tanhf_fast(c);
            h1s[bb][j] = h;
            if (s - 1 == lastidx[bb]) lasth[bb][j] = h;
        }
        __syncthreads();
    }

    // ---- FC head ----
    if (tid < 64) {
        int bb = tid >> 5, j = tid & 31;
        float acc = fc1_b[j];
#pragma unroll
        for (int k = 0; k < LH; k++) acc = fmaf(lasth[bb][k], fc1_w[j * LH + k], acc);
        r1s[bb][j] = fmaxf(acc, 0.f);
    }
    __syncthreads();
    if (tid < 4) {
        int bb = tid >> 1, o = tid & 1;
        float acc = fc2_b[o];
#pragma unroll
        for (int k = 0; k < 32; k++) acc = fmaf(r1s[bb][k], fc2_w[o * 32 + k], acc);
        out[(b0 + bb) * 2 + o] = acc;
    }
}

// ---------------------------------------------------------------------------
extern "C" void kernel_launch(void* const* d_in, const int* in_sizes, int n_in,
                              void* d_out, int out_size)
{
    const float* conn  = (const float*)d_in[0];
    const int*   mask  = (const int*)  d_in[1];
    const float* w1_w  = (const float*)d_in[2];
    const float* w1_b  = (const float*)d_in[3];
    const float* w2_w  = (const float*)d_in[4];
    const float* w2_b  = (const float*)d_in[5];
    const float* Wih0  = (const float*)d_in[6];
    const float* Whh0  = (const float*)d_in[7];
    const float* bih0  = (const float*)d_in[8];
    const float* bhh0  = (const float*)d_in[9];
    const float* Wih1  = (const float*)d_in[10];
    const float* Whh1  = (const float*)d_in[11];
    const float* bih1  = (const float*)d_in[12];
    const float* bhh1  = (const float*)d_in[13];
    const float* fc1_w = (const float*)d_in[14];
    const float* fc1_b = (const float*)d_in[15];
    const float* fc2_w = (const float*)d_in[16];
    const float* fc2_b = (const float*)d_in[17];
    float* out = (float*)d_out;

    encoder_kernel<<<1184, 64>>>(conn, mask, w1_w, w1_b, w2_w, w2_b);
    xg_kernel<<<BT / 64, 256>>>(Wih0, bih0, bhh0);
    lstm_kernel<<<Bb / 2, 384>>>(mask, Whh0, Wih1, Whh1, bih1, bhh1,
                                 fc1_w, fc1_b, fc2_w, fc2_b, out);
}

// round 7
// speedup vs baseline: 1.1685x; 1.1685x over previous
#include <cuda_runtime.h>
#include <cuda_bf16.h>
#include <cstdint>

#define Nn 19
#define GH 64
#define GE 64
#define Bb 256
#define Tt 256
#define BT (Bb*Tt)
#define LH 64
#define G4 256  // 4*LH

typedef unsigned long long ull;

// Scratch (device globals; no allocation allowed)
__device__ float g_emb[(size_t)BT * GE];    // (B*T, 64)
__device__ float g_xg0[(size_t)BT * G4];    // (B*T, 256) = emb@Wih0^T + bih0+bhh0

// ---- packed f32x2 helpers -------------------------------------------------
__device__ __forceinline__ ull pk2(float lo, float hi) {
    ull r; asm("mov.b64 %0, {%1, %2};" : "=l"(r) : "f"(lo), "f"(hi)); return r;
}
__device__ __forceinline__ void upk2(ull v, float& lo, float& hi) {
    asm("mov.b64 {%0, %1}, %2;" : "=f"(lo), "=f"(hi) : "l"(v));
}
__device__ __forceinline__ ull fma2_(ull a, ull b, ull c) {
    ull d; asm("fma.rn.f32x2 %0, %1, %2, %3;" : "=l"(d) : "l"(a), "l"(b), "l"(c));
    return d;
}

__device__ __forceinline__ float sigmoidf_(float x) {
    return __fdividef(1.f, 1.f + __expf(-x));
}
__device__ __forceinline__ float tanhf_fast(float x) {
    x = fmaxf(x, -30.f);
    float e = __expf(-2.f * x);
    return __fdividef(1.f - e, 1.f + e);
}

// ---------------------------------------------------------------------------
// Kernel 1: graph encoder, f32x2-packed along the node dimension.
// Thread j owns feature column j; A/An/X1 stored TRANSPOSED (node index
// innermost, padded 19->20) so node-pairs are contiguous for packed math.
// Weights duplicated into both packed halves, resident in registers.
// ---------------------------------------------------------------------------
__global__ __launch_bounds__(64, 4)
void encoder_kernel(const float* __restrict__ conn, const int* __restrict__ mask,
                    const float* __restrict__ w1_w, const float* __restrict__ w1_b,
                    const float* __restrict__ w2_w, const float* __restrict__ w2_b)
{
    __shared__ __align__(16) float AsT[Nn][20];   // AsT[k][i] = A[i][k]
    __shared__ __align__(16) float AnT[Nn][20];   // AnT[k][i] = An[i][k]
    __shared__ __align__(16) float X1T[GE][20];   // X1T[f][i] = X1[i][f]
    __shared__ float dis[Nn];

    const int tid = threadIdx.x;

    ull w1p[Nn];
#pragma unroll
    for (int k = 0; k < Nn; k++) { float w = w1_w[tid * Nn + k]; w1p[k] = pk2(w, w); }
    ull w2p[GE];
#pragma unroll
    for (int k = 0; k < GE; k++) { float w = w2_w[tid * GE + k]; w2p[k] = pk2(w, w); }
    const float b1 = w1_b[tid], b2 = w2_b[tid];
    const ull b1p = pk2(b1, b1), b2p = pk2(b2, b2);

    // zero the i=19 pad lane once (never rewritten)
    if (tid < Nn) { AsT[tid][19] = 0.f; AnT[tid][19] = 0.f; }

    for (int bt = blockIdx.x; bt < BT; bt += gridDim.x) {
        __syncthreads();  // protect smem reuse across iterations
        const float* A = conn + (size_t)bt * (Nn * Nn);
#pragma unroll
        for (int u = 0; u < 6; u++) {
            int idx = tid + u * 64;
            if (idx < Nn * Nn) { int i = idx / Nn, k = idx - i * Nn; AsT[k][i] = A[idx]; }
        }
        __syncthreads();
        if (tid < Nn) {
            float d = 1.f;  // +I contribution
#pragma unroll
            for (int k = 0; k < Nn; k++) d += AsT[k][tid];
            dis[tid] = rsqrtf(fmaxf(d, 1e-6f));
        }
        __syncthreads();
#pragma unroll
        for (int u = 0; u < 6; u++) {
            int idx = tid + u * 64;
            if (idx < Nn * Nn) {
                int i = idx / Nn, k = idx - i * Nn;
                float a = AsT[k][i] + (i == k ? 1.f : 0.f);
                AnT[k][i] = a * dis[i] * dis[k];
            }
        }
        __syncthreads();

        // ---- H1[i-pair][j] = sum_k A[i][k]*w1[j][k] + b1 ----
        ull acc[10], acc2[10];
#pragma unroll
        for (int ip = 0; ip < 10; ip++) acc[ip] = b1p;
#pragma unroll
        for (int k = 0; k < Nn; k++) {
            const ull w = w1p[k];
            const float4* row = (const float4*)AsT[k];
#pragma unroll
            for (int q = 0; q < 5; q++) {
                float4 v = row[q];
                acc[2*q]   = fma2_(pk2(v.x, v.y), w, acc[2*q]);
                acc[2*q+1] = fma2_(pk2(v.z, v.w), w, acc[2*q+1]);
            }
        }
        // ---- X1 = relu(An @ H1) ----
        float Hs[20];
#pragma unroll
        for (int ip = 0; ip < 10; ip++) upk2(acc[ip], Hs[2*ip], Hs[2*ip+1]);
#pragma unroll
        for (int ip = 0; ip < 10; ip++) acc2[ip] = 0ull;
#pragma unroll
        for (int k = 0; k < Nn; k++) {
            const ull hd = pk2(Hs[k], Hs[k]);
            const float4* row = (const float4*)AnT[k];
#pragma unroll
            for (int q = 0; q < 5; q++) {
                float4 v = row[q];
                acc2[2*q]   = fma2_(pk2(v.x, v.y), hd, acc2[2*q]);
                acc2[2*q+1] = fma2_(pk2(v.z, v.w), hd, acc2[2*q+1]);
            }
        }
#pragma unroll
        for (int ip = 0; ip < 10; ip++) {
            float lo, hi; upk2(acc2[ip], lo, hi);
            float2 s; s.x = fmaxf(lo, 0.f); s.y = fmaxf(hi, 0.f);
            *(float2*)&X1T[tid][2*ip] = s;   // i=19 half computes to 0 (AnT pad)
        }
        __syncthreads();

        // ---- H2[i-pair][j] = sum_f X1[i][f]*w2[j][f] + b2 ----
#pragma unroll
        for (int ip = 0; ip < 10; ip++) acc[ip] = b2p;
#pragma unroll
        for (int k = 0; k < GE; k++) {
            const ull w = w2p[k];
            const float4* row = (const float4*)X1T[k];
#pragma unroll
            for (int q = 0; q < 5; q++) {
                float4 v = row[q];
                acc[2*q]   = fma2_(pk2(v.x, v.y), w, acc[2*q]);
                acc[2*q+1] = fma2_(pk2(v.z, v.w), w, acc[2*q+1]);
            }
        }
        // ---- X2 = relu(An @ H2); mean over nodes; mask ----
#pragma unroll
        for (int ip = 0; ip < 10; ip++) upk2(acc[ip], Hs[2*ip], Hs[2*ip+1]);
#pragma unroll
        for (int ip = 0; ip < 10; ip++) acc2[ip] = 0ull;
#pragma unroll
        for (int k = 0; k < Nn; k++) {
            const ull hd = pk2(Hs[k], Hs[k]);
            const float4* row = (const float4*)AnT[k];
#pragma unroll
            for (int q = 0; q < 5; q++) {
                float4 v = row[q];
                acc2[2*q]   = fma2_(pk2(v.x, v.y), hd, acc2[2*q]);
                acc2[2*q+1] = fma2_(pk2(v.z, v.w), hd, acc2[2*q+1]);
            }
        }
        float s = 0.f;
#pragma unroll
        for (int ip = 0; ip < 10; ip++) {
            float lo, hi; upk2(acc2[ip], lo, hi);
            s += fmaxf(lo, 0.f) + fmaxf(hi, 0.f);   // pad half is 0
        }
        float mf = (float)mask[bt];
        g_emb[(size_t)bt * GE + tid] = s * (1.f / 19.f) * mf;
    }
}

// ---------------------------------------------------------------------------
// Kernel 2: xg0 = emb @ Wih0^T + (bih0+bhh0), f32x2 dot products.
// ---------------------------------------------------------------------------
__global__ __launch_bounds__(256, 2)
void xg_kernel(const float* __restrict__ Wih0, const float* __restrict__ bih0,
               const float* __restrict__ bhh0)
{
    __shared__ __align__(16) float es[64 * GE];
    const int tid = threadIdx.x;
    ull wp[GE / 2];
#pragma unroll
    for (int k2 = 0; k2 < GE / 2; k2++)
        wp[k2] = pk2(Wih0[tid * GE + 2*k2], Wih0[tid * GE + 2*k2 + 1]);
    const float bias = bih0[tid] + bhh0[tid];

    const float* ep = g_emb + (size_t)blockIdx.x * 64 * GE;
    for (int idx = tid; idx < 64 * GE; idx += 256) es[idx] = ep[idx];
    __syncthreads();

    float* op = g_xg0 + (size_t)blockIdx.x * 64 * G4;
    for (int r = 0; r < 64; r++) {
        ull acc = pk2(bias, 0.f);
        const float4* row = (const float4*)&es[r * GE];
#pragma unroll
        for (int q = 0; q < 16; q++) {
            float4 e = row[q];
            acc = fma2_(pk2(e.x, e.y), wp[2*q],     acc);
            acc = fma2_(pk2(e.z, e.w), wp[2*q + 1], acc);
        }
        float lo, hi; upk2(acc, lo, hi);
        op[r * G4 + tid] = lo + hi;
    }
}

// ---------------------------------------------------------------------------
// Kernel 3: fused 2-layer LSTM + FC head (software-pipelined), f32x2 matvecs.
// 128 CTAs x 384 threads = 3 gate groups; each thread owns gates g, g+128
// for 2 batch rows; weights packed along k in registers.
// ---------------------------------------------------------------------------
__global__ __launch_bounds__(384)
void lstm_kernel(const int* __restrict__ mask,
                 const float* __restrict__ Whh0,
                 const float* __restrict__ Wih1, const float* __restrict__ Whh1,
                 const float* __restrict__ bih1, const float* __restrict__ bhh1,
                 const float* __restrict__ fc1_w, const float* __restrict__ fc1_b,
                 const float* __restrict__ fc2_w, const float* __restrict__ fc2_b,
                 float* __restrict__ out)
{
    __shared__ __align__(16) float h0s[2][LH];
    __shared__ __align__(16) float h1s[2][LH];
    __shared__ float c0s[2][LH], c1s[2][LH];
    __shared__ float a0buf[2][G4], p1buf[2][G4], p2buf[2][G4];
    __shared__ float lasth[2][LH];
    __shared__ float r1s[2][32];
    __shared__ int lastidx[2];

    const int tid = threadIdx.x;
    const int m = tid >> 7;       // group 0..2
    const int g = tid & 127;
    const int b0 = blockIdx.x * 2;

    const float* W = (m == 0) ? Whh0 : (m == 1) ? Wih1 : Whh1;
    ull wap[LH / 2], wbp[LH / 2];
#pragma unroll
    for (int k2 = 0; k2 < LH / 2; k2++)
        wap[k2] = pk2(W[g * LH + 2*k2], W[g * LH + 2*k2 + 1]);
#pragma unroll
    for (int k2 = 0; k2 < LH / 2; k2++)
        wbp[k2] = pk2(W[(g + 128) * LH + 2*k2], W[(g + 128) * LH + 2*k2 + 1]);
    float biasA = 0.f, biasB = 0.f;
    if (m == 2) { biasA = bih1[g] + bhh1[g]; biasB = bih1[g + 128] + bhh1[g + 128]; }

    if (tid < 2 * LH) {
        int bb = tid >> 6, j = tid & 63;
        h0s[bb][j] = 0.f; c0s[bb][j] = 0.f;
        h1s[bb][j] = 0.f; c1s[bb][j] = 0.f;
        lasth[bb][j] = 0.f;
    }
    if (tid < 2) {
        const int* mp = mask + (size_t)(b0 + tid) * Tt;
        int sum = 0;
        for (int t = 0; t < Tt; t++) sum += mp[t];
        lastidx[tid] = max(sum, 1) - 1;
    }
    __syncthreads();

    float xga[2], xgb[2];
    if (m == 0) {
#pragma unroll
        for (int bb = 0; bb < 2; bb++) {
            const float* xp = g_xg0 + (size_t)(b0 + bb) * Tt * G4;
            xga[bb] = xp[g]; xgb[bb] = xp[g + 128];
        }
    }

    for (int s = 0; s <= Tt; s++) {
        // ---- compute phase ----
        if (m == 0) {
            if (s < Tt) {
#pragma unroll
                for (int bb = 0; bb < 2; bb++) {
                    ull aA = pk2(xga[bb], 0.f), aB = pk2(xgb[bb], 0.f);
                    const float4* hp = (const float4*)h0s[bb];
#pragma unroll
                    for (int q = 0; q < 16; q++) {
                        float4 h = hp[q];
                        ull p0 = pk2(h.x, h.y), p1 = pk2(h.z, h.w);
                        aA = fma2_(p0, wap[2*q],     aA);
                        aA = fma2_(p1, wap[2*q + 1], aA);
                        aB = fma2_(p0, wbp[2*q],     aB);
                        aB = fma2_(p1, wbp[2*q + 1], aB);
                    }
                    float lo, hi;
                    upk2(aA, lo, hi); a0buf[bb][g]       = lo + hi;
                    upk2(aB, lo, hi); a0buf[bb][g + 128] = lo + hi;
                }
                if (s + 1 < Tt) {
#pragma unroll
                    for (int bb = 0; bb < 2; bb++) {
                        const float* xp = g_xg0 + ((size_t)(b0 + bb) * Tt + (s + 1)) * G4;
                        xga[bb] = xp[g]; xgb[bb] = xp[g + 128];
                    }
                }
            }
        } else if (m == 1) {
            if (s >= 1) {
#pragma unroll
                for (int bb = 0; bb < 2; bb++) {
                    ull aA = 0ull, aB = 0ull;
                    const float4* hp = (const float4*)h0s[bb];
#pragma unroll
                    for (int q = 0; q < 16; q++) {
                        float4 h = hp[q];
                        ull p0 = pk2(h.x, h.y), p1 = pk2(h.z, h.w);
                        aA = fma2_(p0, wap[2*q],     aA);
                        aA = fma2_(p1, wap[2*q + 1], aA);
                        aB = fma2_(p0, wbp[2*q],     aB);
                        aB = fma2_(p1, wbp[2*q + 1], aB);
                    }
                    float lo, hi;
                    upk2(aA, lo, hi); p1buf[bb][g]       = lo + hi;
                    upk2(aB, lo, hi); p1buf[bb][g + 128] = lo + hi;
                }
            }
        } else {
            if (s >= 1) {
#pragma unroll
                for (int bb = 0; bb < 2; bb++) {
                    ull aA = pk2(biasA, 0.f), aB = pk2(biasB, 0.f);
                    const float4* hp = (const float4*)h1s[bb];
#pragma unroll
                    for (int q = 0; q < 16; q++) {
                        float4 h = hp[q];
                        ull p0 = pk2(h.x, h.y), p1 = pk2(h.z, h.w);
                        aA = fma2_(p0, wap[2*q],     aA);
                        aA = fma2_(p1, wap[2*q + 1], aA);
                        aB = fma2_(p0, wbp[2*q],     aB);
                        aB = fma2_(p1, wbp[2*q + 1], aB);
                    }
                    float lo, hi;
                    upk2(aA, lo, hi); p2buf[bb][g]       = lo + hi;
                    upk2(aB, lo, hi); p2buf[bb][g + 128] = lo + hi;
                }
            }
        }
        __syncthreads();

        // ---- update phase ----
        if (m == 0 && s < Tt) {
            int bb = g >> 6, j = g & 63;
            float gi = a0buf[bb][j];
            float gf = a0buf[bb][j + 64];
            float gg = a0buf[bb][j + 128];
            float go = a0buf[bb][j + 192];
            float c = sigmoidf_(gf) * c0s[bb][j] + sigmoidf_(gi) * tanhf_fast(gg);
            c0s[bb][j] = c;
            h0s[bb][j] = sigmoidf_(go) * tanhf_fast(c);
        }
        if (m == 1 && s >= 1) {
            int bb = g >> 6, j = g & 63;
            float gi = p1buf[bb][j]       + p2buf[bb][j];
            float gf = p1buf[bb][j + 64]  + p2buf[bb][j + 64];
            float gg = p1buf[bb][j + 128] + p2buf[bb][j + 128];
            float go = p1buf[bb][j + 192] + p2buf[bb][j + 192];
            float c = sigmoidf_(gf) * c1s[bb][j] + sigmoidf_(gi) * tanhf_fast(gg);
            c1s[bb][j] = c;
            float h = sigmoidf_(go) * tanhf_fast(c);
            h1s[bb][j] = h;
            if (s - 1 == lastidx[bb]) lasth[bb][j] = h;
        }
        __syncthreads();
    }

    // ---- FC head ----
    if (tid < 64) {
        int bb = tid >> 5, j = tid & 31;
        float acc = fc1_b[j];
#pragma unroll
        for (int k = 0; k < LH; k++) acc = fmaf(lasth[bb][k], fc1_w[j * LH + k], acc);
        r1s[bb][j] = fmaxf(acc, 0.f);
    }
    __syncthreads();
    if (tid < 4) {
        int bb = tid >> 1, o = tid & 1;
        float acc = fc2_b[o];
#pragma unroll
        for (int k = 0; k < 32; k++) acc = fmaf(r1s[bb][k], fc2_w[o * 32 + k], acc);
        out[(b0 + bb) * 2 + o] = acc;
    }
}

// ---------------------------------------------------------------------------
extern "C" void kernel_launch(void* const* d_in, const int* in_sizes, int n_in,
                              void* d_out, int out_size)
{
    const float* conn  = (const float*)d_in[0];
    const int*   mask  = (const int*)  d_in[1];
    const float* w1_w  = (const float*)d_in[2];
    const float* w1_b  = (const float*)d_in[3];
    const float* w2_w  = (const float*)d_in[4];
    const float* w2_b  = (const float*)d_in[5];
    const float* Wih0  = (const float*)d_in[6];
    const float* Whh0  = (const float*)d_in[7];
    const float* bih0  = (const float*)d_in[8];
    const float* bhh0  = (const float*)d_in[9];
    const float* Wih1  = (const float*)d_in[10];
    const float* Whh1  = (const float*)d_in[11];
    const float* bih1  = (const float*)d_in[12];
    const float* bhh1  = (const float*)d_in[13];
    const float* fc1_w = (const float*)d_in[14];
    const float* fc1_b = (const float*)d_in[15];
    const float* fc2_w = (const float*)d_in[16];
    const float* fc2_b = (const float*)d_in[17];
    float* out = (float*)d_out;

    encoder_kernel<<<592, 64>>>(conn, mask, w1_w, w1_b, w2_w, w2_b);
    xg_kernel<<<BT / 64, 256>>>(Wih0, bih0, bhh0);
    lstm_kernel<<<Bb / 2, 384>>>(mask, Whh0, Wih1, Whh1, bih1, bhh1,
                                 fc1_w, fc1_b, fc2_w, fc2_b, out);
}

// round 8
// speedup vs baseline: 1.4753x; 1.2626x over previous
#include <cuda_runtime.h>
#include <cuda_bf16.h>
#include <cstdint>

#define Nn 19
#define GH 64
#define GE 64
#define Bb 256
#define Tt 256
#define BT (Bb*Tt)
#define LH 64
#define G4 256  // 4*LH

typedef unsigned long long ull;

// Scratch (device globals; no allocation allowed)
__device__ float g_emb[(size_t)BT * GE];    // (B*T, 64)
__device__ float g_xg0[(size_t)BT * G4];    // (B*T, 256) = emb@Wih0^T + bih0+bhh0

// ---- packed f32x2 helpers -------------------------------------------------
__device__ __forceinline__ ull pk2(float lo, float hi) {
    ull r; asm("mov.b64 %0, {%1, %2};" : "=l"(r) : "f"(lo), "f"(hi)); return r;
}
__device__ __forceinline__ void upk2(ull v, float& lo, float& hi) {
    asm("mov.b64 {%0, %1}, %2;" : "=f"(lo), "=f"(hi) : "l"(v));
}
__device__ __forceinline__ ull fma2_(ull a, ull b, ull c) {
    ull d; asm("fma.rn.f32x2 %0, %1, %2, %3;" : "=l"(d) : "l"(a), "l"(b), "l"(c));
    return d;
}

__device__ __forceinline__ float sigmoidf_(float x) {
    return __fdividef(1.f, 1.f + __expf(-x));
}
__device__ __forceinline__ float tanhf_fast(float x) {
    x = fmaxf(x, -30.f);
    float e = __expf(-2.f * x);
    return __fdividef(1.f - e, 1.f + e);
}

// ---------------------------------------------------------------------------
// Kernel 1: graph encoder. ONE WARP per CTA; thread j owns feature columns
// j and j+32 (so each broadcast LDS.128 feeds 4 FFMA2 instead of 2).
// Node dimension packed in f32x2 (rows padded 19->20). w1 + biases live in
// registers (pre-duplicated pairs); w2 streamed from a padded smem transpose.
// ---------------------------------------------------------------------------
__global__ __launch_bounds__(32, 8)
void encoder_kernel(const float* __restrict__ conn, const int* __restrict__ mask,
                    const float* __restrict__ w1_w, const float* __restrict__ w1_b,
                    const float* __restrict__ w2_w, const float* __restrict__ w2_b)
{
    __shared__ __align__(16) float AsT[Nn][20];   // AsT[k][i] = A[i][k]
    __shared__ __align__(16) float AnT[Nn][20];   // AnT[k][i] = An[i][k]
    __shared__ __align__(16) float X1T[GE][20];   // X1T[f][i]
    __shared__ float dis[20];
    __shared__ float w2s[GE * 65];                // w2s[f*65+j] = w2_w[j][f] (pad 65: conflict-free)

    const int t = threadIdx.x;   // 0..31

    // one-time: transposed copy of w2 into smem (padded stride 65)
    for (int u = 0; u < 128; u++) {
        int idx = t + 32 * u;                 // idx = j*64 + f
        int j = idx >> 6, f = idx & 63;
        w2s[f * 65 + j] = w2_w[idx];
    }
    // pads (never rewritten)
    if (t < Nn) { AsT[t][19] = 0.f; AnT[t][19] = 0.f; }

    // register-resident weights for 2 columns, duplicated pairs
    ull w1a[Nn], w1b[Nn];
#pragma unroll
    for (int k = 0; k < Nn; k++) { float w = w1_w[t * Nn + k];        w1a[k] = pk2(w, w); }
#pragma unroll
    for (int k = 0; k < Nn; k++) { float w = w1_w[(t + 32) * Nn + k]; w1b[k] = pk2(w, w); }
    const float b1a_ = w1_b[t], b1b_ = w1_b[t + 32];
    const ull b1a = pk2(b1a_, b1a_), b1b = pk2(b1b_, b1b_);
    const float b2a_ = w2_b[t], b2b_ = w2_b[t + 32];
    const ull b2a = pk2(b2a_, b2a_), b2b = pk2(b2b_, b2b_);
    __syncwarp();

    for (int bt = blockIdx.x; bt < BT; bt += gridDim.x) {
        // ---- load A (transposed) ----
        const float* A = conn + (size_t)bt * (Nn * Nn);
#pragma unroll
        for (int u = 0; u < 12; u++) {
            int idx = t + u * 32;
            if (idx < Nn * Nn) { int i = idx / Nn, k = idx - i * Nn; AsT[k][i] = A[idx]; }
        }
        __syncwarp();
        // ---- degree normalization ----
        if (t < Nn) {
            float d = 1.f;
#pragma unroll
            for (int k = 0; k < Nn; k++) d += AsT[k][t];
            dis[t] = rsqrtf(fmaxf(d, 1e-6f));
        }
        __syncwarp();
#pragma unroll
        for (int u = 0; u < 12; u++) {
            int idx = t + u * 32;
            if (idx < Nn * Nn) {
                int i = idx / Nn, k = idx - i * Nn;
                float a = AsT[k][i] + (i == k ? 1.f : 0.f);
                AnT[k][i] = a * dis[i] * dis[k];
            }
        }
        __syncwarp();

        // ---- H1 = A@W1^T + b1 (2 cols, node-packed) ----
        ull aA[10], aB[10];
#pragma unroll
        for (int ip = 0; ip < 10; ip++) { aA[ip] = b1a; aB[ip] = b1b; }
#pragma unroll
        for (int k = 0; k < Nn; k++) {
            const float4* row = (const float4*)AsT[k];
            const ull wA = w1a[k], wB = w1b[k];
#pragma unroll
            for (int q = 0; q < 5; q++) {
                float4 v = row[q];
                ull p0 = pk2(v.x, v.y), p1 = pk2(v.z, v.w);
                aA[2*q]   = fma2_(p0, wA, aA[2*q]);
                aA[2*q+1] = fma2_(p1, wA, aA[2*q+1]);
                aB[2*q]   = fma2_(p0, wB, aB[2*q]);
                aB[2*q+1] = fma2_(p1, wB, aB[2*q+1]);
            }
        }
        float HsA[20], HsB[20];
#pragma unroll
        for (int ip = 0; ip < 10; ip++) { upk2(aA[ip], HsA[2*ip], HsA[2*ip+1]); upk2(aB[ip], HsB[2*ip], HsB[2*ip+1]); }

        // ---- X1 = relu(An @ H1), store transposed to smem ----
#pragma unroll
        for (int ip = 0; ip < 10; ip++) { aA[ip] = 0ull; aB[ip] = 0ull; }
#pragma unroll
        for (int k = 0; k < Nn; k++) {
            const float4* row = (const float4*)AnT[k];
            const ull hA = pk2(HsA[k], HsA[k]), hB = pk2(HsB[k], HsB[k]);
#pragma unroll
            for (int q = 0; q < 5; q++) {
                float4 v = row[q];
                ull p0 = pk2(v.x, v.y), p1 = pk2(v.z, v.w);
                aA[2*q]   = fma2_(p0, hA, aA[2*q]);
                aA[2*q+1] = fma2_(p1, hA, aA[2*q+1]);
                aB[2*q]   = fma2_(p0, hB, aB[2*q]);
                aB[2*q+1] = fma2_(p1, hB, aB[2*q+1]);
            }
        }
#pragma unroll
        for (int ip = 0; ip < 10; ip++) {
            float lo, hi;
            upk2(aA[ip], lo, hi);
            { float2 s; s.x = fmaxf(lo, 0.f); s.y = fmaxf(hi, 0.f); *(float2*)&X1T[t][2*ip] = s; }
            upk2(aB[ip], lo, hi);
            { float2 s; s.x = fmaxf(lo, 0.f); s.y = fmaxf(hi, 0.f); *(float2*)&X1T[t + 32][2*ip] = s; }
        }
        __syncwarp();

        // ---- H2 = X1@W2^T + b2 (w2 streamed from smem transpose) ----
#pragma unroll
        for (int ip = 0; ip < 10; ip++) { aA[ip] = b2a; aB[ip] = b2b; }
#pragma unroll 8
        for (int f = 0; f < GE; f++) {
            const float4* row = (const float4*)X1T[f];
            float wAs = w2s[f * 65 + t], wBs = w2s[f * 65 + t + 32];
            const ull wA = pk2(wAs, wAs), wB = pk2(wBs, wBs);
#pragma unroll
            for (int q = 0; q < 5; q++) {
                float4 v = row[q];
                ull p0 = pk2(v.x, v.y), p1 = pk2(v.z, v.w);
                aA[2*q]   = fma2_(p0, wA, aA[2*q]);
                aA[2*q+1] = fma2_(p1, wA, aA[2*q+1]);
                aB[2*q]   = fma2_(p0, wB, aB[2*q]);
                aB[2*q+1] = fma2_(p1, wB, aB[2*q+1]);
            }
        }
#pragma unroll
        for (int ip = 0; ip < 10; ip++) { upk2(aA[ip], HsA[2*ip], HsA[2*ip+1]); upk2(aB[ip], HsB[2*ip], HsB[2*ip+1]); }

        // ---- X2 = relu(An @ H2); mean over nodes; mask ----
#pragma unroll
        for (int ip = 0; ip < 10; ip++) { aA[ip] = 0ull; aB[ip] = 0ull; }
#pragma unroll
        for (int k = 0; k < Nn; k++) {
            const float4* row = (const float4*)AnT[k];
            const ull hA = pk2(HsA[k], HsA[k]), hB = pk2(HsB[k], HsB[k]);
#pragma unroll
            for (int q = 0; q < 5; q++) {
                float4 v = row[q];
                ull p0 = pk2(v.x, v.y), p1 = pk2(v.z, v.w);
                aA[2*q]   = fma2_(p0, hA, aA[2*q]);
                aA[2*q+1] = fma2_(p1, hA, aA[2*q+1]);
                aB[2*q]   = fma2_(p0, hB, aB[2*q]);
                aB[2*q+1] = fma2_(p1, hB, aB[2*q+1]);
            }
        }
        float sA = 0.f, sB = 0.f;
#pragma unroll
        for (int ip = 0; ip < 10; ip++) {
            float lo, hi;
            upk2(aA[ip], lo, hi); sA += fmaxf(lo, 0.f) + fmaxf(hi, 0.f);
            upk2(aB[ip], lo, hi); sB += fmaxf(lo, 0.f) + fmaxf(hi, 0.f);
        }
        const float mf = (float)mask[bt] * (1.f / 19.f);
        g_emb[(size_t)bt * GE + t]      = sA * mf;
        g_emb[(size_t)bt * GE + t + 32] = sB * mf;
        __syncwarp();   // protect AsT/AnT/X1T before next graph's writes
    }
}

// ---------------------------------------------------------------------------
// Kernel 2: xg0 = emb @ Wih0^T + (bih0+bhh0). 2 gate columns per thread
// (t, t+128) so each emb LDS.128 feeds 4 FFMA2.
// ---------------------------------------------------------------------------
__global__ __launch_bounds__(128, 2)
void xg_kernel(const float* __restrict__ Wih0, const float* __restrict__ bih0,
               const float* __restrict__ bhh0)
{
    __shared__ __align__(16) float es[64 * GE];
    const int t = threadIdx.x;
    ull wp1[GE / 2], wp2[GE / 2];
#pragma unroll
    for (int k2 = 0; k2 < GE / 2; k2++)
        wp1[k2] = pk2(Wih0[t * GE + 2*k2], Wih0[t * GE + 2*k2 + 1]);
#pragma unroll
    for (int k2 = 0; k2 < GE / 2; k2++)
        wp2[k2] = pk2(Wih0[(t + 128) * GE + 2*k2], Wih0[(t + 128) * GE + 2*k2 + 1]);
    const float bias1 = bih0[t] + bhh0[t];
    const float bias2 = bih0[t + 128] + bhh0[t + 128];

    const float* ep = g_emb + (size_t)blockIdx.x * 64 * GE;
    for (int idx = t; idx < 64 * GE; idx += 128) es[idx] = ep[idx];
    __syncthreads();

    float* op = g_xg0 + (size_t)blockIdx.x * 64 * G4;
    for (int r = 0; r < 64; r++) {
        ull a1 = pk2(bias1, 0.f), a2 = pk2(bias2, 0.f);
        const float4* row = (const float4*)&es[r * GE];
#pragma unroll
        for (int q = 0; q < 16; q++) {
            float4 e = row[q];
            ull p0 = pk2(e.x, e.y), p1 = pk2(e.z, e.w);
            a1 = fma2_(p0, wp1[2*q],     a1);
            a1 = fma2_(p1, wp1[2*q + 1], a1);
            a2 = fma2_(p0, wp2[2*q],     a2);
            a2 = fma2_(p1, wp2[2*q + 1], a2);
        }
        float lo, hi;
        upk2(a1, lo, hi); op[r * G4 + t]       = lo + hi;
        upk2(a2, lo, hi); op[r * G4 + t + 128] = lo + hi;
    }
}

// ---------------------------------------------------------------------------
// Kernel 3: fused 2-layer LSTM + FC head (unchanged from round 7).
// ---------------------------------------------------------------------------
__global__ __launch_bounds__(384)
void lstm_kernel(const int* __restrict__ mask,
                 const float* __restrict__ Whh0,
                 const float* __restrict__ Wih1, const float* __restrict__ Whh1,
                 const float* __restrict__ bih1, const float* __restrict__ bhh1,
                 const float* __restrict__ fc1_w, const float* __restrict__ fc1_b,
                 const float* __restrict__ fc2_w, const float* __restrict__ fc2_b,
                 float* __restrict__ out)
{
    __shared__ __align__(16) float h0s[2][LH];
    __shared__ __align__(16) float h1s[2][LH];
    __shared__ float c0s[2][LH], c1s[2][LH];
    __shared__ float a0buf[2][G4], p1buf[2][G4], p2buf[2][G4];
    __shared__ float lasth[2][LH];
    __shared__ float r1s[2][32];
    __shared__ int lastidx[2];

    const int tid = threadIdx.x;
    const int m = tid >> 7;
    const int g = tid & 127;
    const int b0 = blockIdx.x * 2;

    const float* W = (m == 0) ? Whh0 : (m == 1) ? Wih1 : Whh1;
    ull wap[LH / 2], wbp[LH / 2];
#pragma unroll
    for (int k2 = 0; k2 < LH / 2; k2++)
        wap[k2] = pk2(W[g * LH + 2*k2], W[g * LH + 2*k2 + 1]);
#pragma unroll
    for (int k2 = 0; k2 < LH / 2; k2++)
        wbp[k2] = pk2(W[(g + 128) * LH + 2*k2], W[(g + 128) * LH + 2*k2 + 1]);
    float biasA = 0.f, biasB = 0.f;
    if (m == 2) { biasA = bih1[g] + bhh1[g]; biasB = bih1[g + 128] + bhh1[g + 128]; }

    if (tid < 2 * LH) {
        int bb = tid >> 6, j = tid & 63;
        h0s[bb][j] = 0.f; c0s[bb][j] = 0.f;
        h1s[bb][j] = 0.f; c1s[bb][j] = 0.f;
        lasth[bb][j] = 0.f;
    }
    if (tid < 2) {
        const int* mp = mask + (size_t)(b0 + tid) * Tt;
        int sum = 0;
        for (int tt = 0; tt < Tt; tt++) sum += mp[tt];
        lastidx[tid] = max(sum, 1) - 1;
    }
    __syncthreads();

    float xga[2], xgb[2];
    if (m == 0) {
#pragma unroll
        for (int bb = 0; bb < 2; bb++) {
            const float* xp = g_xg0 + (size_t)(b0 + bb) * Tt * G4;
            xga[bb] = xp[g]; xgb[bb] = xp[g + 128];
        }
    }

    for (int s = 0; s <= Tt; s++) {
        if (m == 0) {
            if (s < Tt) {
#pragma unroll
                for (int bb = 0; bb < 2; bb++) {
                    ull aA = pk2(xga[bb], 0.f), aB = pk2(xgb[bb], 0.f);
                    const float4* hp = (const float4*)h0s[bb];
#pragma unroll
                    for (int q = 0; q < 16; q++) {
                        float4 h = hp[q];
                        ull p0 = pk2(h.x, h.y), p1 = pk2(h.z, h.w);
                        aA = fma2_(p0, wap[2*q],     aA);
                        aA = fma2_(p1, wap[2*q + 1], aA);
                        aB = fma2_(p0, wbp[2*q],     aB);
                        aB = fma2_(p1, wbp[2*q + 1], aB);
                    }
                    float lo, hi;
                    upk2(aA, lo, hi); a0buf[bb][g]       = lo + hi;
                    upk2(aB, lo, hi); a0buf[bb][g + 128] = lo + hi;
                }
                if (s + 1 < Tt) {
#pragma unroll
                    for (int bb = 0; bb < 2; bb++) {
                        const float* xp = g_xg0 + ((size_t)(b0 + bb) * Tt + (s + 1)) * G4;
                        xga[bb] = xp[g]; xgb[bb] = xp[g + 128];
                    }
                }
            }
        } else if (m == 1) {
            if (s >= 1) {
#pragma unroll
                for (int bb = 0; bb < 2; bb++) {
                    ull aA = 0ull, aB = 0ull;
                    const float4* hp = (const float4*)h0s[bb];
#pragma unroll
                    for (int q = 0; q < 16; q++) {
                        float4 h = hp[q];
                        ull p0 = pk2(h.x, h.y), p1 = pk2(h.z, h.w);
                        aA = fma2_(p0, wap[2*q],     aA);
                        aA = fma2_(p1, wap[2*q + 1], aA);
                        aB = fma2_(p0, wbp[2*q],     aB);
                        aB = fma2_(p1, wbp[2*q + 1], aB);
                    }
                    float lo, hi;
                    upk2(aA, lo, hi); p1buf[bb][g]       = lo + hi;
                    upk2(aB, lo, hi); p1buf[bb][g + 128] = lo + hi;
                }
            }
        } else {
            if (s >= 1) {
#pragma unroll
                for (int bb = 0; bb < 2; bb++) {
                    ull aA = pk2(biasA, 0.f), aB = pk2(biasB, 0.f);
                    const float4* hp = (const float4*)h1s[bb];
#pragma unroll
                    for (int q = 0; q < 16; q++) {
                        float4 h = hp[q];
                        ull p0 = pk2(h.x, h.y), p1 = pk2(h.z, h.w);
                        aA = fma2_(p0, wap[2*q],     aA);
                        aA = fma2_(p1, wap[2*q + 1], aA);
                        aB = fma2_(p0, wbp[2*q],     aB);
                        aB = fma2_(p1, wbp[2*q + 1], aB);
                    }
                    float lo, hi;
                    upk2(aA, lo, hi); p2buf[bb][g]       = lo + hi;
                    upk2(aB, lo, hi); p2buf[bb][g + 128] = lo + hi;
                }
            }
        }
        __syncthreads();

        if (m == 0 && s < Tt) {
            int bb = g >> 6, j = g & 63;
            float gi = a0buf[bb][j];
            float gf = a0buf[bb][j + 64];
            float gg = a0buf[bb][j + 128];
            float go = a0buf[bb][j + 192];
            float c = sigmoidf_(gf) * c0s[bb][j] + sigmoidf_(gi) * tanhf_fast(gg);
            c0s[bb][j] = c;
            h0s[bb][j] = sigmoidf_(go) * tanhf_fast(c);
        }
        if (m == 1 && s >= 1) {
            int bb = g >> 6, j = g & 63;
            float gi = p1buf[bb][j]       + p2buf[bb][j];
            float gf = p1buf[bb][j + 64]  + p2buf[bb][j + 64];
            float gg = p1buf[bb][j + 128] + p2buf[bb][j + 128];
            float go = p1buf[bb][j + 192] + p2buf[bb][j + 192];
            float c = sigmoidf_(gf) * c1s[bb][j] + sigmoidf_(gi) * tanhf_fast(gg);
            c1s[bb][j] = c;
            float h = sigmoidf_(go) * tanhf_fast(c);
            h1s[bb][j] = h;
            if (s - 1 == lastidx[bb]) lasth[bb][j] = h;
        }
        __syncthreads();
    }

    if (tid < 64) {
        int bb = tid >> 5, j = tid & 31;
        float acc = fc1_b[j];
#pragma unroll
        for (int k = 0; k < LH; k++) acc = fmaf(lasth[bb][k], fc1_w[j * LH + k], acc);
        r1s[bb][j] = fmaxf(acc, 0.f);
    }
    __syncthreads();
    if (tid < 4) {
        int bb = tid >> 1, o = tid & 1;
        float acc = fc2_b[o];
#pragma unroll
        for (int k = 0; k < 32; k++) acc = fmaf(r1s[bb][k], fc2_w[o * 32 + k], acc);
        out[(b0 + bb) * 2 + o] = acc;
    }
}

// ---------------------------------------------------------------------------
extern "C" void kernel_launch(void* const* d_in, const int* in_sizes, int n_in,
                              void* d_out, int out_size)
{
    const float* conn  = (const float*)d_in[0];
    const int*   mask  = (const int*)  d_in[1];
    const float* w1_w  = (const float*)d_in[2];
    const float* w1_b  = (const float*)d_in[3];
    const float* w2_w  = (const float*)d_in[4];
    const float* w2_b  = (const float*)d_in[5];
    const float* Wih0  = (const float*)d_in[6];
    const float* Whh0  = (const float*)d_in[7];
    const float* bih0  = (const float*)d_in[8];
    const float* bhh0  = (const float*)d_in[9];
    const float* Wih1  = (const float*)d_in[10];
    const float* Whh1  = (const float*)d_in[11];
    const float* bih1  = (const float*)d_in[12];
    const float* bhh1  = (const float*)d_in[13];
    const float* fc1_w = (const float*)d_in[14];
    const float* fc1_b = (const float*)d_in[15];
    const float* fc2_w = (const float*)d_in[16];
    const float* fc2_b = (const float*)d_in[17];
    float* out = (float*)d_out;

    // Prefer max shared-memory carveout so 8 encoder CTAs (24.9KB each) fit per SM.
    // Idempotent attribute set; safe under graph capture (not a stream op).
    (void)cudaFuncSetAttribute((const void*)encoder_kernel,
                               cudaFuncAttributePreferredSharedMemoryCarveout, 100);

    encoder_kernel<<<1184, 32>>>(conn, mask, w1_w, w1_b, w2_w, w2_b);
    xg_kernel<<<BT / 64, 128>>>(Wih0, bih0, bhh0);
    lstm_kernel<<<Bb / 2, 384>>>(mask, Whh0, Wih1, Whh1, bih1, bhh1,
                                 fc1_w, fc1_b, fc2_w, fc2_b, out);
}